// round 7
// baseline (speedup 1.0000x reference)
#include <cuda_runtime.h>

typedef unsigned long long u64;
#define NPX 16384
#define FULL 0xffffffffu

// Scratch: conv angles + gate coefficients.
// d_coef per block (156 u64): g0 half-packed reg rows @0 (12);
//   g1 A splat @12, B splat @24; g2 lane rows A@36 B@48 (2x6 each);
//   g3..g6 lane 4-row sets @60,84,108,132 (24 each: A rows, B rows).
// d_rl[b*4..]: gate7 scalar rows (A row0, A row1, B row0, B row1).
__device__ float  d_ang[NPX * 8];
__device__ u64    d_coef[780];
__device__ float4 d_rl[20];
__device__ float4 d_initU[2];

// ---------------- packed f32x2 helpers ----------------
__device__ __forceinline__ u64 f2fma(u64 a, u64 b, u64 c) {
    u64 d; asm("fma.rn.f32x2 %0, %1, %2, %3;" : "=l"(d) : "l"(a), "l"(b), "l"(c)); return d;
}
__device__ __forceinline__ u64 f2mul(u64 a, u64 b) {
    u64 d; asm("mul.rn.f32x2 %0, %1, %2;" : "=l"(d) : "l"(a), "l"(b)); return d;
}
__device__ __forceinline__ u64 f2add(u64 a, u64 b) {
    u64 d; asm("add.rn.f32x2 %0, %1, %2;" : "=l"(d) : "l"(a), "l"(b)); return d;
}
__device__ __forceinline__ u64 pk(float a, float b) {
    u64 d; asm("mov.b64 %0, {%1, %2};" : "=l"(d) : "f"(a), "f"(b)); return d;
}
__device__ __forceinline__ void upk(u64 v, float& a, float& b) {
    asm("mov.b64 {%0, %1}, %2;" : "=f"(a), "=f"(b) : "l"(v));
}
__device__ __forceinline__ u64 dup(float v) {
    unsigned u = __float_as_uint(v); return ((u64)u << 32) | (u64)u;
}
__device__ __forceinline__ u64 shfl2(u64 v, int m) {
    float a, b; upk(v, a, b);
    a = __shfl_xor_sync(FULL, a, m);
    b = __shfl_xor_sync(FULL, b, m);
    return pk(a, b);
}
__device__ __forceinline__ u64 f2sub(u64 a, u64 b) { return f2fma(b, dup(-1.0f), a); }

// ---------------- setup helpers ----------------
__device__ __forceinline__ float2 cmul_(float2 a, float2 b) {
    return make_float2(a.x * b.x - a.y * b.y, a.x * b.y + a.y * b.x);
}
__device__ __forceinline__ float2 cadd_(float2 a, float2 b) {
    return make_float2(a.x + b.x, a.y + b.y);
}
__device__ void u3m(const float* p, float2* M) {
    float th = p[0], ph = p[1], la = p[2];
    float s, c;     sincosf(0.5f * th, &s, &c);
    float sl, cl;   sincosf(la, &sl, &cl);
    float sp, cp;   sincosf(ph, &sp, &cp);
    float spl, cpl; sincosf(ph + la, &spl, &cpl);
    M[0] = make_float2(c, 0.0f);
    M[1] = make_float2(-cl * s, -sl * s);
    M[2] = make_float2(cp * s, sp * s);
    M[3] = make_float2(cpl * c, spl * c);
}
__device__ void mm2(const float2* X, const float2* Y, float2* Z) {  // Z = X @ Y
    Z[0] = cadd_(cmul_(X[0], Y[0]), cmul_(X[1], Y[2]));
    Z[1] = cadd_(cmul_(X[0], Y[1]), cmul_(X[1], Y[3]));
    Z[2] = cadd_(cmul_(X[2], Y[0]), cmul_(X[3], Y[2]));
    Z[3] = cadd_(cmul_(X[2], Y[1]), cmul_(X[3], Y[3]));
}
// 12-entry reg-gate row vector from matrix M (normal rows):
// [M0x,-M0y,M1x,-M1y,M0y,M1y, M2x,-M2y,M3x,-M3y,M2y,M3y]
__device__ void rowvec_reg(const float2* M, float* o) {
    o[0]=M[0].x; o[1]=-M[0].y; o[2]=M[1].x; o[3]=-M[1].y; o[4]=M[0].y; o[5]=M[1].y;
    o[6]=M[2].x; o[7]=-M[2].y; o[8]=M[3].x; o[9]=-M[3].y; o[10]=M[2].y; o[11]=M[3].y;
}
// 12-entry lane-gate rows (row0 normal, row1 diag-first)
__device__ void rowvec_lane(const float2* M, float* o) {
    o[0]=M[0].x; o[1]=-M[0].y; o[2]=M[1].x; o[3]=-M[1].y; o[4]=M[0].y; o[5]=M[1].y;
    o[6]=M[3].x; o[7]=-M[3].y; o[8]=M[2].x; o[9]=-M[2].y; o[10]=M[3].y; o[11]=M[2].y;
}

// ---------------------------------------------------------------------------
// Kernel 1: conv (4 threads/pixel, packed f32x2) + last block: gate setup.
// ---------------------------------------------------------------------------
__global__ void __launch_bounds__(128)
conv_kernel(const float* __restrict__ x, const float* __restrict__ cw,
            const float* __restrict__ cb, const float* __restrict__ u3p,
            const float* __restrict__ cu3p) {
    if (blockIdx.x == gridDim.x - 1) {
        int t = threadIdx.x;
        if (t == 40) {
            float2 M[4]; u3m(u3p, M);
            d_initU[0] = make_float4(M[0].x, M[0].y, M[1].x, M[1].y);
            d_initU[1] = make_float4(M[2].x, M[2].y, M[3].x, M[3].y);
        }
        if (t < 40) {
            int b = t >> 3, w = t & 7;
            float2 U[4], C[4], B[4];
            if (w < 7)      u3m(u3p + (b * 8 + w + 1) * 3, U);
            else if (b < 4) u3m(u3p + ((b + 1) * 8) * 3, U);
            else { U[0] = make_float2(1, 0); U[1] = make_float2(0, 0);
                   U[2] = make_float2(0, 0); U[3] = make_float2(1, 0); }
            u3m(cu3p + (b * 8 + w) * 3, C);
            if (w < 7) mm2(C, U, B);
            else       mm2(U, C, B);
            u64* base = d_coef + b * 156;
            float va[12], vb[12];
            if (w == 0) {
                rowvec_reg(U, va); rowvec_reg(B, vb);
                for (int i = 0; i < 12; i++) base[i] = pk(va[i], vb[i]);
            } else if (w == 1) {
                rowvec_reg(U, va); rowvec_reg(B, vb);
                for (int i = 0; i < 12; i++) { base[12+i] = dup(va[i]); base[24+i] = dup(vb[i]); }
            } else if (w < 7) {
                u64* d = base + 36 + (w - 2) * 24;
                rowvec_lane(U, va); rowvec_lane(B, vb);
                for (int i = 0; i < 12; i++) { d[i] = dup(va[i]); d[12+i] = dup(vb[i]); }
            } else {
                d_rl[b*4+0] = make_float4(U[0].x, U[0].y, U[1].x, U[1].y);
                d_rl[b*4+1] = make_float4(U[2].x, U[2].y, U[3].x, U[3].y);
                d_rl[b*4+2] = make_float4(B[0].x, B[0].y, B[1].x, B[1].y);
                d_rl[b*4+3] = make_float4(B[2].x, B[2].y, B[3].x, B[3].y);
            }
        }
        return;
    }
    __shared__ __align__(16) float wq[1152];   // wq[widx*8 + q]
    int tid = threadIdx.x;
    for (int i = tid; i < 1152; i += 128) {
        int q = i / 144, widx = i % 144;
        wq[widx * 8 + q] = cw[i];
    }
    __syncthreads();

    int sub = (tid >> 3) & 3;
    int p   = blockIdx.x * 32 + (tid & 7) + ((tid >> 5) << 3);
    int bN = p >> 12, h = (p >> 6) & 63, wd = p & 63;

    u64 ACC[4] = {0, 0, 0, 0};
#pragma unroll
    for (int cc = 0; cc < 4; cc++) {
        int ci = sub * 4 + cc;
        const float* xp = x + ((bN * 16 + ci) << 12);
#pragma unroll
        for (int kh = 0; kh < 3; kh++) {
            int hh = h + kh - 1;
            if (hh < 0 || hh > 63) continue;
#pragma unroll
            for (int kw = 0; kw < 3; kw++) {
                int ww = wd + kw - 1;
                if (ww < 0 || ww > 63) continue;
                u64 xv2 = dup(xp[hh * 64 + ww]);
                const u64* wp_ = (const u64*)(wq + (ci * 9 + kh * 3 + kw) * 8);
                ACC[0] = f2fma(xv2, wp_[0], ACC[0]);
                ACC[1] = f2fma(xv2, wp_[1], ACC[1]);
                ACC[2] = f2fma(xv2, wp_[2], ACC[2]);
                ACC[3] = f2fma(xv2, wp_[3], ACC[3]);
            }
        }
    }
#pragma unroll
    for (int j = 0; j < 4; j++) {
        ACC[j] = f2add(ACC[j], shfl2(ACC[j], 8));
        ACC[j] = f2add(ACC[j], shfl2(ACC[j], 16));
    }
    float lo, hi; upk(ACC[sub], lo, hi);
    int q0 = sub * 2;
    *(float2*)&d_ang[p * 8 + q0] = make_float2(lo + cb[q0], hi + cb[q0 + 1]);
}

// ---------------------------------------------------------------------------
// Packed state: one pixel/warp. 256 amps: lane bits 0..4 = wires 7..3;
// reg index j = k-bits {0,1} = wires 2,1; u64 halves = kb2 (wire 0): low k=j, high k=j+4.
// ---------------------------------------------------------------------------
__device__ __forceinline__ void cpair2(u64& a0r, u64& a0i, u64& a1r, u64& a1i,
                                       const u64* r) {
    u64 n0r = f2fma(r[0], a0r, f2fma(r[1], a0i, f2fma(r[2],  a1r, f2mul(r[3],  a1i))));
    u64 n0i = f2fma(r[4], a0r, f2fma(r[0], a0i, f2fma(r[5],  a1r, f2mul(r[2],  a1i))));
    u64 n1r = f2fma(r[6], a0r, f2fma(r[7], a0i, f2fma(r[8],  a1r, f2mul(r[9],  a1i))));
    u64 n1i = f2fma(r[10],a0r, f2fma(r[6], a0i, f2fma(r[11], a1r, f2mul(r[8],  a1i))));
    a0r = n0r; a0i = n0i; a1r = n1r; a1i = n1i;
}
__device__ __forceinline__ void cpair_s(float& a0r, float& a0i, float& a1r, float& a1i,
                                        float2 u00, float2 u01, float2 u10, float2 u11) {
    float n0r = u00.x * a0r - u00.y * a0i + u01.x * a1r - u01.y * a1i;
    float n0i = u00.x * a0i + u00.y * a0r + u01.x * a1i + u01.y * a1r;
    float n1r = u10.x * a0r - u10.y * a0i + u11.x * a1r - u11.y * a1i;
    float n1i = u10.x * a0i + u10.y * a0r + u11.x * a1i + u11.y * a1r;
    a0r = n0r; a0i = n0i; a1r = n1r; a1i = n1i;
}
__device__ __forceinline__ void lrow(u64& ar, u64& ai, int msk,
                                     u64 c0, u64 c1, u64 c2, u64 c3, u64 c4, u64 c5) {
    u64 xr = shfl2(ar, msk), xi = shfl2(ai, msk);
    u64 nr = f2fma(c0, ar, f2fma(c1, ai, f2fma(c2, xr, f2mul(c3, xi))));
    u64 ni = f2fma(c4, ar, f2fma(c0, ai, f2fma(c5, xr, f2mul(c2, xi))));
    ar = nr; ai = ni;
}
__device__ __forceinline__ float wsum(float x) {
#pragma unroll
    for (int o = 16; o; o >>= 1) x += __shfl_xor_sync(FULL, x, o);
    return x;
}
// lane-wire X/Y partials, halves folded -> scalar
template <int MSK>
__device__ __forceinline__ void xy_l(const u64* AR, const u64* AI, int lane,
                                     float& uo, float& vo) {
    u64 uu = 0, vp = 0, vm = 0;
#pragma unroll
    for (int j = 0; j < 4; j++) {
        u64 xr = shfl2(AR[j], MSK), xi = shfl2(AI[j], MSK);
        uu = f2fma(AR[j], xr, f2fma(AI[j], xi, uu));
        vp = f2fma(AI[j], xr, vp);
        vm = f2fma(AR[j], xi, vm);
    }
    float a, b; upk(uu, a, b); uo = a + b;
    u64 vv = f2sub(vp, vm);
    upk(vv, a, b); float v = a + b;
    vo = (lane & MSK) ? -v : v;
}

// ---------------------------------------------------------------------------
// Kernel 2: one warp per pixel, k-packed f32x2 statevector.
// ---------------------------------------------------------------------------
__global__ void __launch_bounds__(128)
sim_kernel(const float* __restrict__ fc_w, const float* __restrict__ fc_b,
           float* __restrict__ out) {
    __shared__ u64 sco[780];
    __shared__ float4 srl[20];
    __shared__ float4 sinit[2];
    int t = threadIdx.x, wp = t >> 5, lane = t & 31;
    int pix = blockIdx.x * 4 + wp;

    for (int i = t; i < 780; i += 128) sco[i] = d_coef[i];
    if (t < 20) srl[t] = d_rl[t];
    if (t < 2)  sinit[t] = d_initU[t];

    float mys = 0.0f, myc = 1.0f;
    if (lane < 8) {
        float a = d_ang[pix * 8 + lane];
        sincosf(0.5f * a, &mys, &myc);
    }
    float cw[8], sw_[8];
#pragma unroll
    for (int w = 0; w < 8; w++) {
        cw[w]  = __shfl_sync(FULL, myc, w);
        sw_[w] = __shfl_sync(FULL, mys, w);
    }
    float lf = 1.0f;
#pragma unroll
    for (int q = 0; q < 5; q++)                    // lane bits 0..4 = wires 7..3
        lf *= ((lane >> q) & 1) ? sw_[7 - q] : cw[7 - q];
    __syncthreads();

    // fold U3(block0, wire0) into the wire-0 initial vector
    float4 M0 = sinit[0], M1 = sinit[1];
    float v0r = M0.x * cw[0] + M0.z * sw_[0];
    float v0i = M0.y * cw[0] + M0.w * sw_[0];
    float v1r = M1.x * cw[0] + M1.z * sw_[0];
    float v1i = M1.y * cw[0] + M1.w * sw_[0];

    u64 AR[4], AI[4];
#pragma unroll
    for (int j = 0; j < 4; j++) {
        float rp = lf * ((j & 1) ? sw_[2] : cw[2]) * ((j & 2) ? sw_[1] : cw[1]);
        AR[j] = pk(rp * v0r, rp * v1r);
        AI[j] = pk(rp * v0i, rp * v1i);
    }

    // 5 blocks of 8 fused CU3 gates
#pragma unroll 1
    for (int b = 0; b < 5; b++) {
        const u64* gb = sco + b * 156;
        // g0: c=kb2(halves), t=kb1 -> half-packed coeffs
        cpair2(AR[0], AI[0], AR[2], AI[2], gb);
        cpair2(AR[1], AI[1], AR[3], AI[3], gb);
        // g1: c=kb1, t=kb0
        cpair2(AR[0], AI[0], AR[1], AI[1], gb + 12);
        cpair2(AR[2], AI[2], AR[3], AI[3], gb + 24);
        // g2: c=kb0, t=lane4
        {
            int tb = (lane >> 4) & 1;
            const u64* rA = gb + 36 + tb * 6;
            const u64* rB = gb + 48 + tb * 6;
            u64 a0=rA[0],a1=rA[1],a2=rA[2],a3=rA[3],a4=rA[4],a5=rA[5];
            u64 b0=rB[0],b1=rB[1],b2=rB[2],b3=rB[3],b4=rB[4],b5=rB[5];
            lrow(AR[0], AI[0], 16, a0,a1,a2,a3,a4,a5);
            lrow(AR[1], AI[1], 16, b0,b1,b2,b3,b4,b5);
            lrow(AR[2], AI[2], 16, a0,a1,a2,a3,a4,a5);
            lrow(AR[3], AI[3], 16, b0,b1,b2,b3,b4,b5);
        }
        // g3..g6: lane ctrl/target
        {
            const u64* g3 = gb + 60;
            const u64* r = g3 + ((((lane >> 4) & 1) << 1) | ((lane >> 3) & 1)) * 6;
            u64 c0=r[0],c1=r[1],c2=r[2],c3=r[3],c4=r[4],c5=r[5];
#pragma unroll
            for (int j = 0; j < 4; j++) lrow(AR[j], AI[j], 8, c0,c1,c2,c3,c4,c5);
        }
        {
            const u64* g4 = gb + 84;
            const u64* r = g4 + ((((lane >> 3) & 1) << 1) | ((lane >> 2) & 1)) * 6;
            u64 c0=r[0],c1=r[1],c2=r[2],c3=r[3],c4=r[4],c5=r[5];
#pragma unroll
            for (int j = 0; j < 4; j++) lrow(AR[j], AI[j], 4, c0,c1,c2,c3,c4,c5);
        }
        {
            const u64* g5 = gb + 108;
            const u64* r = g5 + ((((lane >> 2) & 1) << 1) | ((lane >> 1) & 1)) * 6;
            u64 c0=r[0],c1=r[1],c2=r[2],c3=r[3],c4=r[4],c5=r[5];
#pragma unroll
            for (int j = 0; j < 4; j++) lrow(AR[j], AI[j], 2, c0,c1,c2,c3,c4,c5);
        }
        {
            const u64* g6 = gb + 132;
            const u64* r = g6 + ((((lane >> 1) & 1) << 1) | (lane & 1)) * 6;
            u64 c0=r[0],c1=r[1],c2=r[2],c3=r[3],c4=r[4],c5=r[5];
#pragma unroll
            for (int j = 0; j < 4; j++) lrow(AR[j], AI[j], 1, c0,c1,c2,c3,c4,c5);
        }
        // g7: c=lane0, t=kb2 (cross-half, scalar 2x2)
        {
            const float4* M = &srl[b * 4 + ((lane & 1) ? 2 : 0)];
            float4 r0 = M[0], r1 = M[1];
            float2 u00 = make_float2(r0.x, r0.y), u01 = make_float2(r0.z, r0.w);
            float2 u10 = make_float2(r1.x, r1.y), u11 = make_float2(r1.z, r1.w);
#pragma unroll
            for (int j = 0; j < 4; j++) {
                float aLr, aHr, aLi, aHi;
                upk(AR[j], aLr, aHr); upk(AI[j], aLi, aHi);
                cpair_s(aLr, aLi, aHr, aHi, u00, u01, u10, u11);
                AR[j] = pk(aLr, aHr); AI[j] = pk(aLi, aHi);
            }
        }
    }

    // ---- direct Pauli measurement ----
    u64 PP[4];
#pragma unroll
    for (int j = 0; j < 4; j++) PP[j] = f2fma(AR[j], AR[j], f2mul(AI[j], AI[j]));
    u64 s01 = f2add(PP[0], PP[1]), s23 = f2add(PP[2], PP[3]);
    u64 Tp  = f2add(s01, s23);
    float tL, tH; upk(Tp, tL, tH);
    float tt = tL + tH;
    float z0 = tL - tH;                                    // wire0 (halves)
    float za, zb;
    upk(f2sub(s01, s23), za, zb); float z1 = za + zb;      // wire1 (j bit1)
    upk(f2sub(f2add(PP[0], PP[2]), f2add(PP[1], PP[3])), za, zb);
    float z2 = za + zb;                                    // wire2 (j bit0)

    // Walsh-Hadamard of tt over lane bits: W(2^q) lands on lane 2^q
    float wt = tt;
#pragma unroll
    for (int o = 1; o <= 16; o <<= 1) {
        float r = __shfl_xor_sync(FULL, wt, o);
        wt = (lane & o) ? (r - wt) : (wt + r);
    }

    // wire0 X/Y: cross-half products (scalar)
    float u0 = 0.0f, v0 = 0.0f;
#pragma unroll
    for (int j = 0; j < 4; j++) {
        float aLr, aHr, aLi, aHi;
        upk(AR[j], aLr, aHr); upk(AI[j], aLi, aHi);
        u0 += aLr * aHr + aLi * aHi;
        v0 += aLi * aHr - aLr * aHi;
    }
    // wire1 (pairs (K0,K2),(K1,K3)) packed
    float u1, v1, u2, v2;
    {
        u64 up = f2fma(AR[0], AR[2], f2fma(AI[0], AI[2],
                 f2fma(AR[1], AR[3], f2mul(AI[1], AI[3]))));
        u64 vp = f2fma(AI[0], AR[2], f2mul(AI[1], AR[3]));
        u64 vm = f2fma(AR[0], AI[2], f2mul(AR[1], AI[3]));
        float a, b; upk(up, a, b); u1 = a + b;
        upk(f2sub(vp, vm), a, b); v1 = a + b;
    }
    // wire2 (pairs (K0,K1),(K2,K3)) packed
    {
        u64 up = f2fma(AR[0], AR[1], f2fma(AI[0], AI[1],
                 f2fma(AR[2], AR[3], f2mul(AI[2], AI[3]))));
        u64 vp = f2fma(AI[0], AR[1], f2mul(AI[2], AR[3]));
        u64 vm = f2fma(AR[0], AI[1], f2mul(AR[2], AI[3]));
        float a, b; upk(up, a, b); u2 = a + b;
        upk(f2sub(vp, vm), a, b); v2 = a + b;
    }
    // lane wires
    float ul0, vl0, ul1, vl1, ul2, vl2, ul3, vl3, ul4, vl4;
    xy_l<1>(AR, AI, lane, ul0, vl0);    // wire7
    xy_l<2>(AR, AI, lane, ul1, vl1);    // wire6
    xy_l<4>(AR, AI, lane, ul2, vl2);    // wire5
    xy_l<8>(AR, AI, lane, ul3, vl3);    // wire4
    xy_l<16>(AR, AI, lane, ul4, vl4);   // wire3

    // scalar butterfly reductions (warp-uniform results)
    float mz0 = wsum(z0), mz1 = wsum(z1), mz2 = wsum(z2);
    float mx0 = 2.0f * wsum(u0), mx1 = 2.0f * wsum(u1), mx2 = 2.0f * wsum(u2);
    float my0 = 2.0f * wsum(v0), my1 = 2.0f * wsum(v1), my2 = 2.0f * wsum(v2);
    float mx3 = wsum(ul4), mx4 = wsum(ul3), mx5 = wsum(ul2);
    float mx6 = wsum(ul1), mx7 = wsum(ul0);
    float my3 = wsum(vl4), my4 = wsum(vl3), my5 = wsum(vl2);
    float my6 = wsum(vl1), my7 = wsum(vl0);
    float mz3 = __shfl_sync(FULL, wt, 16);
    float mz4 = __shfl_sync(FULL, wt, 8);
    float mz5 = __shfl_sync(FULL, wt, 4);
    float mz6 = __shfl_sync(FULL, wt, 2);
    float mz7 = __shfl_sync(FULL, wt, 1);

    // fused FC: one lane per output channel
    const float4* fw4 = (const float4*)fc_w + lane * 6;
    float4 w0 = __ldg(fw4 + 0), w1 = __ldg(fw4 + 1), w2 = __ldg(fw4 + 2);
    float4 w3 = __ldg(fw4 + 3), w4 = __ldg(fw4 + 4), w5 = __ldg(fw4 + 5);
    float o = __ldg(&fc_b[lane]);
    o += w0.x * mz0 + w0.y * mz1 + w0.z * mz2 + w0.w * mz3;
    o += w1.x * mz4 + w1.y * mz5 + w1.z * mz6 + w1.w * mz7;
    o += w2.x * mx0 + w2.y * mx1 + w2.z * mx2 + w2.w * mx3;
    o += w3.x * mx4 + w3.y * mx5 + w3.z * mx6 + w3.w * mx7;
    o += w4.x * my0 + w4.y * my1 + w4.z * my2 + w4.w * my3;
    o += w5.x * my4 + w5.y * my5 + w5.z * my6 + w5.w * my7;

    int bN = pix >> 12, hw = pix & 4095;
    out[(bN * 32 + lane) * 4096 + hw] = o;
}

// ---------------------------------------------------------------------------
extern "C" void kernel_launch(void* const* d_in, const int* in_sizes, int n_in,
                              void* d_out, int out_size) {
    const float* x      = (const float*)d_in[0];
    const float* conv_w = (const float*)d_in[1];
    const float* conv_b = (const float*)d_in[2];
    const float* u3p    = (const float*)d_in[3];
    const float* cu3p   = (const float*)d_in[4];
    const float* fc_w   = (const float*)d_in[5];
    const float* fc_b   = (const float*)d_in[6];
    float* out = (float*)d_out;

    conv_kernel<<<NPX / 32 + 1, 128>>>(x, conv_w, conv_b, u3p, cu3p);
    sim_kernel<<<NPX / 4, 128>>>(fc_w, fc_b, out);
}